// round 8
// baseline (speedup 1.0000x reference)
#include <cuda_runtime.h>
#include <cuda_fp16.h>

#define NN   5000            // nodes per level
#define BB   1024            // batch
#define KK   16              // fan-in
#define NLEV 9               // level applications
#define NEG_SLOPE 0.1f

#define KSM  148             // smem-path blocks (one per SM, wave 1)
#define CH   4               // batch lanes per smem block
#define LS   (KSM * CH)      // 592 lanes via smem path
#define WQ   (BB - LS)       // 432 lanes via L2 worker path
#define WPACK (WQ / 8)       // 54 uint4 packs per activation row
#define NWORK 148            // worker blocks (one per SM, wave 2)
#define GRID (KSM + NWORK)   // 296 = 2 x 148 -> all resident
#define NTHR 512

// worker-path fp16 activations [N, WQ], ping-pong (uint4 = 8 halves): 8.64 MB
__device__ uint4 g_wact[2][NN * WPACK];
// packed params: (fp16 weight << 16) | u16 idx : 2.88 MB
__device__ unsigned int g_par[NLEV * NN * KK];
// worker inter-level barrier counters (zeroed every launch)
__device__ int g_bar[NLEV];

// ---------------------------------------------------------------------------
__global__ void prep_kernel(const int* __restrict__ sidx, const float* __restrict__ w) {
    int i = blockIdx.x * 256 + threadIdx.x;
    if (i < NLEV * NN * KK) {
        unsigned short wb = __half_as_ushort(__float2half_rn(w[i]));
        g_par[i] = ((unsigned int)wb << 16) | (unsigned short)sidx[i];
    }
    if (i < NLEV) g_bar[i] = 0;
}

// transpose x lanes [LS, BB) -> g_wact[0] [N, WQ] fp16
__global__ void tin_w_kernel(const float* __restrict__ x) {
    __shared__ float tile[32][33];
    int n  = blockIdx.x * 32 + threadIdx.x;
    int wl = blockIdx.y * 32 + threadIdx.y;
    if (n < NN && wl < WQ) tile[threadIdx.y][threadIdx.x] = x[(LS + wl) * NN + n];
    __syncthreads();
    int wl2 = blockIdx.y * 32 + threadIdx.x;
    int n2  = blockIdx.x * 32 + threadIdx.y;
    if (n2 < NN && wl2 < WQ) {
        __half* h = reinterpret_cast<__half*>(g_wact[0]);
        h[n2 * WQ + wl2] = __float2half_rn(tile[threadIdx.x][threadIdx.y]);
    }
}

// transpose final worker activations g_wact[1] -> out lanes [LS, BB)
__global__ void tout_w_kernel(float* __restrict__ out) {
    __shared__ float tile[32][33];
    int wl = blockIdx.x * 32 + threadIdx.x;
    int n  = blockIdx.y * 32 + threadIdx.y;
    if (n < NN && wl < WQ) {
        const __half* h = reinterpret_cast<const __half*>(g_wact[NLEV & 1]);
        tile[threadIdx.y][threadIdx.x] = __half2float(h[n * WQ + wl]);
    }
    __syncthreads();
    int n2  = blockIdx.y * 32 + threadIdx.x;
    int wl2 = blockIdx.x * 32 + threadIdx.y;
    if (n2 < NN && wl2 < WQ) out[(LS + wl2) * NN + n2] = tile[threadIdx.x][threadIdx.y];
}

// ---------------------------------------------------------------------------
#define LEAKY(a) ((a) > 0.0f ? (a) : NEG_SLOPE * (a))

// smem-path gather-accumulate: 4 lanes from one uint2 (4 fp16)
#define GAS(u) do {                                                        \
    unsigned s_ = (u) & 0xFFFFu;                                           \
    float w_ = __half2float(__ushort_as_half((unsigned short)((u) >> 16)));\
    uint2 v_ = src[s_];                                                    \
    float2 f0_ = __half22float2(*reinterpret_cast<const __half2*>(&v_.x)); \
    float2 f1_ = __half22float2(*reinterpret_cast<const __half2*>(&v_.y)); \
    a0 = fmaf(f0_.x, w_, a0);  a1 = fmaf(f0_.y, w_, a1);                   \
    a2 = fmaf(f1_.x, w_, a2);  a3 = fmaf(f1_.y, w_, a3);                   \
} while (0)

__global__ __launch_bounds__(NTHR, 2) void topo_kernel(
    const float* __restrict__ x,      // [B, N]
    const float* __restrict__ bias,   // [NLEV, N]
    float* __restrict__ out)          // [B, N]
{
    extern __shared__ __align__(16) uint2 sb[];   // [2][NN] (smem path only)
    const int t = threadIdx.x;

    if (blockIdx.x < KSM) {
        // ================= SMEM path: batch lanes [c*CH, c*CH+CH) ==========
        const int c = blockIdx.x;
        uint2* b0 = sb;
        uint2* b1 = sb + NN;

        // prologue: x -> fp16 slice
        for (int n = t; n < NN; n += NTHR) {
            float v0 = x[(c * CH + 0) * NN + n];
            float v1 = x[(c * CH + 1) * NN + n];
            float v2 = x[(c * CH + 2) * NN + n];
            float v3 = x[(c * CH + 3) * NN + n];
            __half2 h01 = __floats2half2_rn(v0, v1);
            __half2 h23 = __floats2half2_rn(v2, v3);
            uint2 o;
            o.x = *reinterpret_cast<unsigned int*>(&h01);
            o.y = *reinterpret_cast<unsigned int*>(&h23);
            b0[n] = o;
        }
        __syncthreads();

        const uint2* src = b0;
        uint2* dst = b1;
        for (int l = 0; l < NLEV; l++) {
            const uint4* pp = reinterpret_cast<const uint4*>(g_par + (size_t)l * NN * KK);
            const float* bb = bias + (size_t)l * NN;
            for (int n = t; n < NN; n += NTHR) {
                uint4 p0 = pp[n * 4 + 0];
                uint4 p1 = pp[n * 4 + 1];
                uint4 p2 = pp[n * 4 + 2];
                uint4 p3 = pp[n * 4 + 3];
                float bv = bb[n];
                float a0 = bv, a1 = bv, a2 = bv, a3 = bv;
                GAS(p0.x); GAS(p0.y); GAS(p0.z); GAS(p0.w);
                GAS(p1.x); GAS(p1.y); GAS(p1.z); GAS(p1.w);
                GAS(p2.x); GAS(p2.y); GAS(p2.z); GAS(p2.w);
                GAS(p3.x); GAS(p3.y); GAS(p3.z); GAS(p3.w);
                a0 = LEAKY(a0); a1 = LEAKY(a1); a2 = LEAKY(a2); a3 = LEAKY(a3);
                __half2 h01 = __floats2half2_rn(a0, a1);
                __half2 h23 = __floats2half2_rn(a2, a3);
                uint2 o;
                o.x = *reinterpret_cast<unsigned int*>(&h01);
                o.y = *reinterpret_cast<unsigned int*>(&h23);
                dst[n] = o;
            }
            __syncthreads();
            const uint2* tmp = src; src = dst; dst = const_cast<uint2*>(tmp);
        }

        // epilogue: final slice (in src after last swap) -> out, coalesced per lane
        for (int n = t; n < NN; n += NTHR) {
            uint2 v = src[n];
            float2 f0 = __half22float2(*reinterpret_cast<const __half2*>(&v.x));
            float2 f1 = __half22float2(*reinterpret_cast<const __half2*>(&v.y));
            out[(c * CH + 0) * NN + n] = f0.x;
            out[(c * CH + 1) * NN + n] = f0.y;
            out[(c * CH + 2) * NN + n] = f1.x;
            out[(c * CH + 3) * NN + n] = f1.y;
        }
    } else {
        // ================= L2 worker path: lanes [LS, BB), node-split ======
        const int wi = blockIdx.x - KSM;
        const int chunk = (NN + NWORK - 1) / NWORK;    // 34
        const int n0 = wi * chunk;
        const int n1 = (n0 + chunk < NN) ? (n0 + chunk) : NN;
        const int tasks = (n1 > n0) ? (n1 - n0) * WPACK : 0;

        int sel = 0;
        for (int l = 0; l < NLEV; l++) {
            const uint4* __restrict__ srcg = g_wact[sel];
            uint4* __restrict__ dstg       = g_wact[sel ^ 1];
            const unsigned int* __restrict__ parl = g_par + (size_t)l * NN * KK;
            const float* __restrict__ bb = bias + (size_t)l * NN;

            for (int f = t; f < tasks; f += NTHR) {
                int n = n0 + f / WPACK;
                int p = f % WPACK;
                const unsigned int* pr = parl + n * KK;
                float bv = bb[n];
                float a0 = bv, a1 = bv, a2 = bv, a3 = bv;
                float a4 = bv, a5 = bv, a6 = bv, a7 = bv;
#pragma unroll
                for (int k = 0; k < KK; k++) {
                    unsigned int u = __ldg(pr + k);
                    unsigned s = u & 0xFFFFu;
                    float wk = __half2float(__ushort_as_half((unsigned short)(u >> 16)));
                    uint4 v = __ldcg(srcg + s * WPACK + p);   // L2-only: no stale L1
                    float2 f0 = __half22float2(*reinterpret_cast<const __half2*>(&v.x));
                    float2 f1 = __half22float2(*reinterpret_cast<const __half2*>(&v.y));
                    float2 f2 = __half22float2(*reinterpret_cast<const __half2*>(&v.z));
                    float2 f3 = __half22float2(*reinterpret_cast<const __half2*>(&v.w));
                    a0 = fmaf(f0.x, wk, a0);  a1 = fmaf(f0.y, wk, a1);
                    a2 = fmaf(f1.x, wk, a2);  a3 = fmaf(f1.y, wk, a3);
                    a4 = fmaf(f2.x, wk, a4);  a5 = fmaf(f2.y, wk, a5);
                    a6 = fmaf(f3.x, wk, a6);  a7 = fmaf(f3.y, wk, a7);
                }
                a0 = LEAKY(a0); a1 = LEAKY(a1); a2 = LEAKY(a2); a3 = LEAKY(a3);
                a4 = LEAKY(a4); a5 = LEAKY(a5); a6 = LEAKY(a6); a7 = LEAKY(a7);
                __half2 h0 = __floats2half2_rn(a0, a1);
                __half2 h1 = __floats2half2_rn(a2, a3);
                __half2 h2 = __floats2half2_rn(a4, a5);
                __half2 h3 = __floats2half2_rn(a6, a7);
                uint4 o;
                o.x = *reinterpret_cast<unsigned int*>(&h0);
                o.y = *reinterpret_cast<unsigned int*>(&h1);
                o.z = *reinterpret_cast<unsigned int*>(&h2);
                o.w = *reinterpret_cast<unsigned int*>(&h3);
                dstg[n * WPACK + p] = o;
            }

            // inter-level barrier among the NWORK worker blocks
            __threadfence();
            __syncthreads();
            if (t == 0) {
                atomicAdd(&g_bar[l], 1);
                while (*(volatile int*)&g_bar[l] < NWORK) __nanosleep(100);
                __threadfence();
            }
            __syncthreads();
            sel ^= 1;
        }
        // final worker result in g_wact[NLEV & 1]; tout_w_kernel writes it out
    }
}

// ---------------------------------------------------------------------------
extern "C" void kernel_launch(void* const* d_in, const int* in_sizes, int n_in,
                              void* d_out, int out_size) {
    const float* x    = (const float*)d_in[0];   // [B, N] fp32
    const int*   sidx = (const int*)d_in[1];     // [NLEV, N, K] int32
    const float* w    = (const float*)d_in[2];   // [NLEV, N, K] fp32
    const float* bias = (const float*)d_in[3];   // [NLEV, N]    fp32
    float* out = (float*)d_out;                  // [B, N] fp32

    const int smem_bytes = 2 * NN * 8;           // 80,000 B ping-pong (smem path)
    cudaFuncSetAttribute(topo_kernel, cudaFuncAttributeMaxDynamicSharedMemorySize, smem_bytes);

    int tot = NLEV * NN * KK;
    prep_kernel<<<(tot + 255) / 256, 256>>>(sidx, w);

    dim3 tblk(32, 32);
    dim3 tin_grid((NN + 31) / 32, (WQ + 31) / 32);
    tin_w_kernel<<<tin_grid, tblk>>>(x);

    topo_kernel<<<GRID, NTHR, smem_bytes>>>(x, bias, out);

    dim3 tout_grid((WQ + 31) / 32, (NN + 31) / 32);
    tout_w_kernel<<<tout_grid, tblk>>>(out);
}

// round 10
// speedup vs baseline: 1.5595x; 1.5595x over previous
#include <cuda_runtime.h>
#include <cuda_fp16.h>

#define NN 5000      // nodes per level
#define BB 1024      // batch
#define KK 16        // fan-in
#define NLEV 9       // level applications
#define NEG_SLOPE 0.1f

#define NGRID 888    // level-kernel blocks (grid-stride, 6/SM)
#define NTHR  256    // 2 node-groups of 128 threads

// fp16 activation planes, [N, B] node-major, ping-pong: 2 x 10.24 MB.
__device__ __align__(16) __half g_act[2][NN * BB];
// packed params: (fp16 weight << 16) | u16 idx : 2.88 MB
__device__ __align__(16) unsigned int g_par[NLEV * NN * KK];

// ---------------------------------------------------------------------------
__global__ void prep_kernel(const int* __restrict__ sidx, const float* __restrict__ w) {
    int i = blockIdx.x * 256 + threadIdx.x;
    if (i < NLEV * NN * KK) {
        unsigned short wb = __half_as_ushort(__float2half_rn(w[i]));
        g_par[i] = ((unsigned int)wb << 16) | (unsigned short)sidx[i];
    }
}

// Transpose input x [B, N] fp32 -> g_act[0] [N, B] fp16
__global__ void tin_kernel(const float* __restrict__ x) {
    __shared__ float tile[32][33];
    int n = blockIdx.x * 32 + threadIdx.x;
    int b = blockIdx.y * 32 + threadIdx.y;
    if (n < NN) tile[threadIdx.y][threadIdx.x] = x[b * NN + n];
    __syncthreads();
    int b2 = blockIdx.y * 32 + threadIdx.x;
    int n2 = blockIdx.x * 32 + threadIdx.y;
    if (n2 < NN) g_act[0][n2 * BB + b2] = __float2half_rn(tile[threadIdx.x][threadIdx.y]);
}

// ---------------------------------------------------------------------------
#define LEAKY(a) ((a) > 0.0f ? (a) : NEG_SLOPE * (a))

// one edge: warp-uniform packed param u, gather 8 halves (LDG.128), 8 fp32 FMA
#define EDGE(u) do {                                                        \
    float wk = __half2float(__ushort_as_half((unsigned short)((u) >> 16))); \
    const float4* row = reinterpret_cast<const float4*>(src + ((u) & 0xFFFFu) * BB); \
    float4 v = __ldg(row + t);                                              \
    float2 f0 = __half22float2(*reinterpret_cast<const __half2*>(&v.x));    \
    float2 f1 = __half22float2(*reinterpret_cast<const __half2*>(&v.y));    \
    float2 f2 = __half22float2(*reinterpret_cast<const __half2*>(&v.z));    \
    float2 f3 = __half22float2(*reinterpret_cast<const __half2*>(&v.w));    \
    a0 = fmaf(f0.x, wk, a0);  a1 = fmaf(f0.y, wk, a1);                      \
    a2 = fmaf(f1.x, wk, a2);  a3 = fmaf(f1.y, wk, a3);                      \
    a4 = fmaf(f2.x, wk, a4);  a5 = fmaf(f2.y, wk, a5);                      \
    a6 = fmaf(f3.x, wk, a6);  a7 = fmaf(f3.y, wk, a7);                      \
} while (0)

// Grid-stride level kernel: 256 threads = 2 independent groups of 128.
// A group handles one node: 128 threads x 8 fp16 lanes = 1024 batch.
__global__ __launch_bounds__(NTHR) void level_kernel(int ssel, int lev,
                                                     const float* __restrict__ bias_all) {
    const __half* __restrict__ src = g_act[ssel];
    __half*       __restrict__ dst = g_act[ssel ^ 1];
    const unsigned int* __restrict__ par = g_par + (size_t)lev * NN * KK;   // device-side symbol access
    const float* __restrict__ bias = bias_all + (size_t)lev * NN;

    const int t   = threadIdx.x & 127;            // lane within group
    const int sub = threadIdx.x >> 7;             // group 0/1

    for (int n = blockIdx.x * 2 + sub; n < NN; n += NGRID * 2) {
        // params: warp-uniform loads (L1 broadcast), 4 x uint4 = 16 edges
        const uint4* pp = reinterpret_cast<const uint4*>(par + n * KK);
        uint4 p0 = __ldg(pp + 0);
        uint4 p1 = __ldg(pp + 1);
        uint4 p2 = __ldg(pp + 2);
        uint4 p3 = __ldg(pp + 3);
        float bv = __ldg(bias + n);

        float a0 = bv, a1 = bv, a2 = bv, a3 = bv;
        float a4 = bv, a5 = bv, a6 = bv, a7 = bv;

        EDGE(p0.x); EDGE(p0.y); EDGE(p0.z); EDGE(p0.w);
        EDGE(p1.x); EDGE(p1.y); EDGE(p1.z); EDGE(p1.w);
        EDGE(p2.x); EDGE(p2.y); EDGE(p2.z); EDGE(p2.w);
        EDGE(p3.x); EDGE(p3.y); EDGE(p3.z); EDGE(p3.w);

        a0 = LEAKY(a0); a1 = LEAKY(a1); a2 = LEAKY(a2); a3 = LEAKY(a3);
        a4 = LEAKY(a4); a5 = LEAKY(a5); a6 = LEAKY(a6); a7 = LEAKY(a7);

        __half2 h0 = __floats2half2_rn(a0, a1);
        __half2 h1 = __floats2half2_rn(a2, a3);
        __half2 h2 = __floats2half2_rn(a4, a5);
        __half2 h3 = __floats2half2_rn(a6, a7);
        float4 o;
        o.x = __uint_as_float(*reinterpret_cast<unsigned int*>(&h0));
        o.y = __uint_as_float(*reinterpret_cast<unsigned int*>(&h1));
        o.z = __uint_as_float(*reinterpret_cast<unsigned int*>(&h2));
        o.w = __uint_as_float(*reinterpret_cast<unsigned int*>(&h3));
        reinterpret_cast<float4*>(dst + n * BB)[t] = o;
    }
}

// Reconstruct + transpose final plane -> out [B, N] fp32
__global__ void tout_kernel(int sel, float* __restrict__ out) {
    __shared__ float tile[32][33];
    int b = blockIdx.x * 32 + threadIdx.x;
    int n = blockIdx.y * 32 + threadIdx.y;
    if (n < NN) tile[threadIdx.y][threadIdx.x] = __half2float(g_act[sel][n * BB + b]);
    __syncthreads();
    int n2 = blockIdx.y * 32 + threadIdx.x;
    int b2 = blockIdx.x * 32 + threadIdx.y;
    if (n2 < NN) out[b2 * NN + n2] = tile[threadIdx.x][threadIdx.y];
}

// ---------------------------------------------------------------------------
extern "C" void kernel_launch(void* const* d_in, const int* in_sizes, int n_in,
                              void* d_out, int out_size) {
    const float* x    = (const float*)d_in[0];   // [B, N] fp32
    const int*   sidx = (const int*)d_in[1];     // [NLEV, N, K] int32
    const float* w    = (const float*)d_in[2];   // [NLEV, N, K] fp32
    const float* bias = (const float*)d_in[3];   // [NLEV, N]    fp32
    float* out = (float*)d_out;                  // [B, N] fp32

    int tot = NLEV * NN * KK;
    prep_kernel<<<(tot + 255) / 256, 256>>>(sidx, w);

    dim3 tblk(32, 32);
    dim3 tin_grid((NN + 31) / 32, BB / 32);
    tin_kernel<<<tin_grid, tblk>>>(x);

    for (int l = 0; l < NLEV; l++) {
        level_kernel<<<NGRID, NTHR>>>(l & 1, l, bias);
    }

    dim3 tout_grid(BB / 32, (NN + 31) / 32);
    tout_kernel<<<tout_grid, tblk>>>(NLEV & 1, out);
}